// round 1
// baseline (speedup 1.0000x reference)
#include <cuda_runtime.h>
#include <math.h>

// Pipeline (per batch element b):
//   x[21,7]      <- build from state24[b]
//   gl1,gr1      <- x @ Wl1 / Wr1           [21,256]
//   e1[i,j,h]    <- att1 . lrelu(gl1[j]+gr1[i])  (h=4 heads, d=64)
//   alpha1       <- softmax_j(e1)
//   h1           <- elu(alpha1 @ gl1 + b1)  [21,256]   (stored over gr1)
//   gl2,gr2      <- h1 @ Wl2 / Wr2          [21,64]    (stored over gl1)
//   e2,alpha2    <- 1-head attention
//   out2         <- alpha2 @ gl2 + b2       [21,64]    (stored over gr1)
//   nfv          <- mean_i out2             [64]
//   fc1,fc2,fc3  -> tanh -> out[b,2]

#define NTHREADS 256

__global__ __launch_bounds__(NTHREADS) void actor_kernel(
    const float* __restrict__ state24,
    const float* __restrict__ Wl1, const float* __restrict__ Wr1,
    const float* __restrict__ att1, const float* __restrict__ b1,
    const float* __restrict__ Wl2, const float* __restrict__ Wr2,
    const float* __restrict__ att2, const float* __restrict__ b2,
    const float* __restrict__ fc1w, const float* __restrict__ fc1b,
    const float* __restrict__ fc2w, const float* __restrict__ fc2b,
    const float* __restrict__ fc3w, const float* __restrict__ fc3b,
    float* __restrict__ out)
{
    extern __shared__ float sm[];
    float* sAtt1 = sm;            // 256
    float* sB1   = sAtt1 + 256;   // 256
    float* sAtt2 = sB1   + 256;   // 64
    float* sB2   = sAtt2 + 64;    // 64
    float* sX    = sB2   + 64;    // 168 (21*8)
    float* sGL1  = sX    + 168;   // 5376 (21*256)
    float* sGR1  = sGL1  + 5376;  // 5376 (21*256) -> later h1, later out2
    float* sE1   = sGR1  + 5376;  // 1764 (21*21*4) -> later nfv/f1/f2
    // layer-2 aliases living in the (dead after step E) sGL1 region:
    float* sGL2 = sGL1;           // 1344 (21*64)
    float* sGR2 = sGL1 + 1344;    // 1344
    float* sE2  = sGL1 + 2688;    // 441
    // fc aliases living in the (dead after step E) sE1 region:
    float* sNFV = sE1;            // 64
    float* sF1  = sE1 + 64;       // 256
    float* sF2  = sE1 + 320;      // 256

    const int tid  = threadIdx.x;
    const int lane = tid & 31;
    const int b    = blockIdx.x;
    const float* st = state24 + b * 24;

    // ---- load small constants to smem ----
    sAtt1[tid] = att1[tid];
    sB1[tid]   = b1[tid];
    if (tid < 64) { sAtt2[tid] = att2[tid]; sB2[tid] = b2[tid]; }

    // ---- build node features ----
    if (tid < 21) {
        float f0, f1, f2, f3, f4, f5, f6;
        if (tid < 20) {
            // angles[i] = (-pi/2 - 0.03) + i*((pi+0.03)/20) + pi/20   (float32 math in ref)
            double ang = (-1.6007963267948966 + 0.15707963267948966)
                       + (double)tid * 0.15857963267948968;
            float a = (float)ang;
            f0 = st[tid] * 0.1f;
            f1 = sinf(a); f2 = cosf(a);
            f3 = f4 = f5 = f6 = 0.f;
        } else {
            f0 = f1 = f2 = 0.f;
            f3 = st[20]; f4 = st[21]; f5 = st[22]; f6 = st[23];
        }
        float* xr = sX + tid * 8;
        xr[0]=f0; xr[1]=f1; xr[2]=f2; xr[3]=f3; xr[4]=f4; xr[5]=f5; xr[6]=f6; xr[7]=0.f;
    }
    __syncthreads();

    // ---- Step B: gl1 / gr1 = x @ Wl1 / Wr1  (thread = column c) ----
    {
        const int c = tid;
        float wl[7], wr[7];
        #pragma unroll
        for (int k = 0; k < 7; k++) { wl[k] = Wl1[k*256 + c]; wr[k] = Wr1[k*256 + c]; }
        #pragma unroll 3
        for (int i = 0; i < 21; i++) {
            const float* xr = sX + i * 8;
            float al = 0.f, ar = 0.f;
            #pragma unroll
            for (int k = 0; k < 7; k++) { float xv = xr[k]; al = fmaf(xv, wl[k], al); ar = fmaf(xv, wr[k], ar); }
            sGL1[i*256 + c] = al;
            sGR1[i*256 + c] = ar;
        }
    }
    __syncthreads();

    // ---- Step C: attention logits e1[i,j,h]  (lane-rotated d-loop: conflict-free) ----
    for (int idx = tid; idx < 21*21*4; idx += NTHREADS) {
        const int h = idx & 3;
        const int p = idx >> 2;           // i*21 + j
        const int j = p % 21, i = p / 21;
        const float* gl = sGL1 + j*256 + h*64;
        const float* gr = sGR1 + i*256 + h*64;
        const float* at = sAtt1 + h*64;
        float e = 0.f;
        #pragma unroll 8
        for (int dd = 0; dd < 64; dd++) {
            int d = (dd + lane) & 63;
            float s = gl[d] + gr[d];
            s = fmaxf(s, 0.2f * s);       // leaky_relu(0.2), branchless
            e = fmaf(at[d], s, e);
        }
        sE1[idx] = e;                     // layout [i][j][h]
    }
    __syncthreads();

    // ---- Step D: softmax over j for each (i,h) ----
    if (tid < 84) {
        const int i = tid >> 2, h = tid & 3;
        float* row = sE1 + i*84 + h;      // stride 4
        float m = -1e30f;
        for (int j = 0; j < 21; j++) m = fmaxf(m, row[j*4]);
        float sum = 0.f;
        for (int j = 0; j < 21; j++) { float v = expf(row[j*4] - m); row[j*4] = v; sum += v; }
        float inv = 1.f / sum;
        for (int j = 0; j < 21; j++) row[j*4] *= inv;
    }
    __syncthreads();

    // ---- Step E: h1 = elu(alpha1 @ gl1 + b1)  -> overwrite sGR1 ----
    {
        const int c = tid, h = c >> 6;
        #pragma unroll 3
        for (int i = 0; i < 21; i++) {
            const float* al = sE1 + i*84 + h;
            float acc = 0.f;
            #pragma unroll 7
            for (int j = 0; j < 21; j++) acc = fmaf(al[j*4], sGL1[j*256 + c], acc);
            float v = acc + sB1[c];
            v = (v > 0.f) ? v : expm1f(v);    // elu
            sGR1[i*256 + c] = v;
        }
    }
    __syncthreads();

    // ---- Step F: gl2 / gr2 = h1 @ Wl2 / Wr2  ([21,256]x[256,64]) ----
    {
        const int d    = tid & 63;
        const int sel  = (tid >> 6) & 1;
        const int half = tid >> 7;
        const float* __restrict__ W = sel ? Wr2 : Wl2;
        float* G = sel ? sGR2 : sGL2;
        const int i0 = half ? 11 : 0;
        float acc[11];
        #pragma unroll
        for (int i = 0; i < 11; i++) acc[i] = 0.f;
        for (int k = 0; k < 256; k += 4) {
            const float w0 = W[(k+0)*64 + d];
            const float w1 = W[(k+1)*64 + d];
            const float w2 = W[(k+2)*64 + d];
            const float w3 = W[(k+3)*64 + d];
            #pragma unroll
            for (int i = 0; i < 11; i++) {
                if (i0 + i < 21) {
                    float4 hv = *(const float4*)&sGR1[(i0+i)*256 + k];
                    acc[i] = fmaf(hv.x, w0, acc[i]);
                    acc[i] = fmaf(hv.y, w1, acc[i]);
                    acc[i] = fmaf(hv.z, w2, acc[i]);
                    acc[i] = fmaf(hv.w, w3, acc[i]);
                }
            }
        }
        #pragma unroll
        for (int i = 0; i < 11; i++)
            if (i0 + i < 21) G[(i0+i)*64 + d] = acc[i];
    }
    __syncthreads();

    // ---- Step C2: e2[i,j] (single head) ----
    for (int idx = tid; idx < 441; idx += NTHREADS) {
        const int j = idx % 21, i = idx / 21;
        const float* gl = sGL2 + j*64;
        const float* gr = sGR2 + i*64;
        float e = 0.f;
        #pragma unroll 8
        for (int dd = 0; dd < 64; dd++) {
            int d = (dd + lane) & 63;
            float s = gl[d] + gr[d];
            s = fmaxf(s, 0.2f * s);
            e = fmaf(sAtt2[d], s, e);
        }
        sE2[idx] = e;
    }
    __syncthreads();

    // ---- softmax2 ----
    if (tid < 21) {
        float* row = sE2 + tid*21;
        float m = -1e30f;
        for (int j = 0; j < 21; j++) m = fmaxf(m, row[j]);
        float sum = 0.f;
        for (int j = 0; j < 21; j++) { float v = expf(row[j] - m); row[j] = v; sum += v; }
        float inv = 1.f / sum;
        for (int j = 0; j < 21; j++) row[j] *= inv;
    }
    __syncthreads();

    // ---- Step E2: out2 = alpha2 @ gl2 + b2  -> sGR1 region ----
    float* sOUT2 = sGR1;
    for (int o = tid; o < 1344; o += NTHREADS) {
        const int i = o >> 6, d = o & 63;
        const float* al = sE2 + i*21;
        float acc = 0.f;
        #pragma unroll 7
        for (int j = 0; j < 21; j++) acc = fmaf(al[j], sGL2[j*64 + d], acc);
        sOUT2[o] = acc + sB2[d];
    }
    __syncthreads();

    // ---- global mean pool ----
    if (tid < 64) {
        float acc = 0.f;
        #pragma unroll 7
        for (int i = 0; i < 21; i++) acc += sOUT2[i*64 + tid];
        sNFV[tid] = acc * (1.0f / 21.0f);
    }
    __syncthreads();

    // ---- fc1 (64->256) + relu ----
    {
        const int c = tid;
        float acc = fc1b[c];
        #pragma unroll 8
        for (int k = 0; k < 64; k++) acc = fmaf(sNFV[k], fc1w[k*256 + c], acc);
        sF1[c] = fmaxf(acc, 0.f);
    }
    __syncthreads();

    // ---- fc2 (256->256) + relu ----
    {
        const int c = tid;
        float acc = fc2b[c];
        #pragma unroll 8
        for (int k = 0; k < 256; k++) acc = fmaf(sF1[k], fc2w[k*256 + c], acc);
        sF2[c] = fmaxf(acc, 0.f);
    }
    __syncthreads();

    // ---- fc3 (256->2) + tanh : 2 warps, warp-reduced ----
    if (tid < 64) {
        const int o = tid >> 5;
        const int l = tid & 31;
        float acc = 0.f;
        #pragma unroll
        for (int k = l; k < 256; k += 32) acc = fmaf(sF2[k], fc3w[k*2 + o], acc);
        #pragma unroll
        for (int off = 16; off; off >>= 1) acc += __shfl_down_sync(0xffffffffu, acc, off);
        if (l == 0) out[b*2 + o] = tanhf(acc + fc3b[o]);
    }
}

extern "C" void kernel_launch(void* const* d_in, const int* in_sizes, int n_in,
                              void* d_out, int out_size) {
    const float* state24 = (const float*)d_in[0];
    const float* Wl1  = (const float*)d_in[1];
    const float* Wr1  = (const float*)d_in[2];
    const float* att1 = (const float*)d_in[3];
    const float* b1   = (const float*)d_in[4];
    const float* Wl2  = (const float*)d_in[5];
    const float* Wr2  = (const float*)d_in[6];
    const float* att2 = (const float*)d_in[7];
    const float* b2   = (const float*)d_in[8];
    const float* fc1w = (const float*)d_in[9];
    const float* fc1b = (const float*)d_in[10];
    const float* fc2w = (const float*)d_in[11];
    const float* fc2b = (const float*)d_in[12];
    const float* fc3w = (const float*)d_in[13];
    const float* fc3b = (const float*)d_in[14];
    float* out = (float*)d_out;

    const int B = in_sizes[0] / 24;
    const size_t smem = 13324 * sizeof(float);  // 53,296 bytes
    cudaFuncSetAttribute(actor_kernel, cudaFuncAttributeMaxDynamicSharedMemorySize, (int)smem);
    actor_kernel<<<B, NTHREADS, smem>>>(state24, Wl1, Wr1, att1, b1,
                                        Wl2, Wr2, att2, b2,
                                        fc1w, fc1b, fc2w, fc2b, fc3w, fc3b, out);
}

// round 2
// speedup vs baseline: 1.1676x; 1.1676x over previous
#include <cuda_runtime.h>
#include <math.h>

#define NTHREADS 256

// ---- f32x2 packed-FMA helpers (sm_100+) ----
__device__ __forceinline__ unsigned long long pk2(float a, float b) {
    unsigned long long r;
    asm("mov.b64 %0, {%1,%2};" : "=l"(r) : "f"(a), "f"(b));
    return r;
}
__device__ __forceinline__ float2 upk2(unsigned long long v) {
    float2 r;
    asm("mov.b64 {%0,%1}, %2;" : "=f"(r.x), "=f"(r.y) : "l"(v));
    return r;
}
__device__ __forceinline__ unsigned long long fma2(unsigned long long a,
                                                   unsigned long long b,
                                                   unsigned long long c) {
    unsigned long long d;
    asm("fma.rn.f32x2 %0, %1, %2, %3;" : "=l"(d) : "l"(a), "l"(b), "l"(c));
    return d;
}

// smem layout (floats)
#define OFF_ATT1 0      // 256
#define OFF_B1   256    // 256
#define OFF_ATT2 512    // 64
#define OFF_B2   576    // 64
#define OFF_WR1  640    // 1792 (7x256)
#define OFF_X    2432   // 168 (21x8)
#define OFF_AJ   2600   // 88
#define OFF_GL1  2688   // 5376 (21x256) -> h1 after step E
#define OFF_SCR  8064   // 3200 scratch
#define SMEM_FLOATS 11264

// scratch sublayout:
//  raw e1 logits:   [i*84 + j*4 + h]            (1764)   (step C -> D reads)
//  alphaT:          [h*462 + j*22 + i]          (1848)   (D writes -> E reads)
//  layer2: gl2 @0 (1344), gr2 @1344 (1344), e2 @2688 (441)
//  out2 @1344 (1344) after C2; fc: nfv @0(64), f1 @64(256), f2 @320(256)

__global__ __launch_bounds__(NTHREADS, 5) void actor_kernel(
    const float* __restrict__ state24,
    const float* __restrict__ Wl1, const float* __restrict__ Wr1,
    const float* __restrict__ att1, const float* __restrict__ b1,
    const float* __restrict__ Wl2, const float* __restrict__ Wr2,
    const float* __restrict__ att2, const float* __restrict__ b2,
    const float* __restrict__ fc1w, const float* __restrict__ fc1b,
    const float* __restrict__ fc2w, const float* __restrict__ fc2b,
    const float* __restrict__ fc3w, const float* __restrict__ fc3b,
    float* __restrict__ out)
{
    extern __shared__ float sm[];
    float* sAtt1 = sm + OFF_ATT1;
    float* sB1   = sm + OFF_B1;
    float* sAtt2 = sm + OFF_ATT2;
    float* sB2   = sm + OFF_B2;
    float* sWr1  = sm + OFF_WR1;
    float* sX    = sm + OFF_X;
    float* sAj   = sm + OFF_AJ;
    float* sGL1  = sm + OFF_GL1;   // later h1
    float* sSCR  = sm + OFF_SCR;

    const int tid  = threadIdx.x;
    const int lane = tid & 31;
    const int warp = tid >> 5;
    const int b    = blockIdx.x;
    const float* st = state24 + b * 24;

    // ---- consts + Wr1 -> smem, node features ----
    sAtt1[tid] = att1[tid];
    sB1[tid]   = b1[tid];
    if (tid < 64) { sAtt2[tid] = att2[tid]; sB2[tid] = b2[tid]; }
    #pragma unroll
    for (int i = tid; i < 1792; i += NTHREADS) sWr1[i] = Wr1[i];

    if (tid < 21) {
        float f0, f1, f2, f3, f4, f5, f6;
        if (tid < 20) {
            double ang = (-1.6007963267948966 + 0.15707963267948966)
                       + (double)tid * 0.15857963267948968;
            float a = (float)ang;
            f0 = st[tid] * 0.1f;
            f1 = sinf(a); f2 = cosf(a);
            f3 = f4 = f5 = f6 = 0.f;
        } else {
            f0 = f1 = f2 = 0.f;
            f3 = st[20]; f4 = st[21]; f5 = st[22]; f6 = st[23];
        }
        float* xr = sX + tid * 8;
        xr[0]=f0; xr[1]=f1; xr[2]=f2; xr[3]=f3; xr[4]=f4; xr[5]=f5; xr[6]=f6; xr[7]=0.f;
    }
    __syncthreads();

    // ---- B: gl1 = x @ Wl1 (thread = column c) ----
    {
        const int c = tid;
        float wl[7];
        #pragma unroll
        for (int k = 0; k < 7; k++) wl[k] = Wl1[k*256 + c];
        #pragma unroll 3
        for (int i = 0; i < 21; i++) {
            const float* xr = sX + i*8;
            float a = 0.f;
            #pragma unroll
            for (int k = 0; k < 7; k++) a = fmaf(xr[k], wl[k], a);
            sGL1[i*256 + c] = a;
        }
    }
    __syncthreads();

    // ---- Aj precompute: A[j,h] = att1[h] . gl1[j, h*64: ] ----
    {
        float4 aA = *(const float4*)&sAtt1[8*lane];
        float4 aB = *(const float4*)&sAtt1[8*lane + 4];
        for (int j = warp; j < 21; j += 8) {
            float4 g0 = *(const float4*)&sGL1[j*256 + 8*lane];
            float4 g1 = *(const float4*)&sGL1[j*256 + 8*lane + 4];
            float p = aA.x*g0.x + aA.y*g0.y + aA.z*g0.z + aA.w*g0.w
                    + aB.x*g1.x + aB.y*g1.y + aB.z*g1.z + aB.w*g1.w;
            p += __shfl_xor_sync(0xffffffffu, p, 4);
            p += __shfl_xor_sync(0xffffffffu, p, 2);
            p += __shfl_xor_sync(0xffffffffu, p, 1);
            if ((lane & 7) == 0) sAj[j*4 + (lane >> 3)] = p;
        }
    }
    __syncthreads();

    // ---- C: e1[i,j,h] = 0.6(A_j + B_i) + 0.4 * sum_d att |gl+gr|  ----
    {
        float4 aA = *(const float4*)&sAtt1[8*lane];
        float4 aB = *(const float4*)&sAtt1[8*lane + 4];
        float* sE1 = sSCR;
        for (int i = warp; i < 21; i += 8) {
            // gr1[i, lane dims] on the fly from x @ Wr1
            float4 r0 = make_float4(0.f,0.f,0.f,0.f);
            float4 r1 = make_float4(0.f,0.f,0.f,0.f);
            #pragma unroll
            for (int m = 0; m < 7; m++) {
                float xv = sX[i*8 + m];
                float4 w0 = *(const float4*)&sWr1[m*256 + 8*lane];
                float4 w1 = *(const float4*)&sWr1[m*256 + 8*lane + 4];
                r0.x = fmaf(xv, w0.x, r0.x); r0.y = fmaf(xv, w0.y, r0.y);
                r0.z = fmaf(xv, w0.z, r0.z); r0.w = fmaf(xv, w0.w, r0.w);
                r1.x = fmaf(xv, w1.x, r1.x); r1.y = fmaf(xv, w1.y, r1.y);
                r1.z = fmaf(xv, w1.z, r1.z); r1.w = fmaf(xv, w1.w, r1.w);
            }
            float Bp = aA.x*r0.x + aA.y*r0.y + aA.z*r0.z + aA.w*r0.w
                     + aB.x*r1.x + aB.y*r1.y + aB.z*r1.z + aB.w*r1.w;
            Bp += __shfl_xor_sync(0xffffffffu, Bp, 4);
            Bp += __shfl_xor_sync(0xffffffffu, Bp, 2);
            Bp += __shfl_xor_sync(0xffffffffu, Bp, 1);

            #pragma unroll 3
            for (int j = 0; j < 21; j++) {
                float4 g0 = *(const float4*)&sGL1[j*256 + 8*lane];
                float4 g1 = *(const float4*)&sGL1[j*256 + 8*lane + 4];
                float t;
                t  = aA.x * fabsf(g0.x + r0.x);
                t  = fmaf(aA.y, fabsf(g0.y + r0.y), t);
                t  = fmaf(aA.z, fabsf(g0.z + r0.z), t);
                t  = fmaf(aA.w, fabsf(g0.w + r0.w), t);
                t  = fmaf(aB.x, fabsf(g1.x + r1.x), t);
                t  = fmaf(aB.y, fabsf(g1.y + r1.y), t);
                t  = fmaf(aB.z, fabsf(g1.z + r1.z), t);
                t  = fmaf(aB.w, fabsf(g1.w + r1.w), t);
                t += __shfl_xor_sync(0xffffffffu, t, 4);
                t += __shfl_xor_sync(0xffffffffu, t, 2);
                t += __shfl_xor_sync(0xffffffffu, t, 1);
                if ((lane & 7) == 0) {
                    int h = lane >> 3;
                    sE1[(i*21 + j)*4 + h] =
                        fmaf(0.4f, t, 0.6f * (sAj[j*4 + h] + Bp));
                }
            }
        }
    }
    __syncthreads();

    // ---- D: softmax over j; write transposed alpha [h*462 + j*22 + i] ----
    {
        float v[21];
        const int i = tid >> 2, h = tid & 3;
        if (tid < 84) {
            const float* row = sSCR + i*84 + h;
            float m = -1e30f;
            #pragma unroll
            for (int j = 0; j < 21; j++) { v[j] = row[j*4]; m = fmaxf(m, v[j]); }
            float s = 0.f;
            #pragma unroll
            for (int j = 0; j < 21; j++) { v[j] = __expf(v[j] - m); s += v[j]; }
            float inv = 1.f / s;
            #pragma unroll
            for (int j = 0; j < 21; j++) v[j] *= inv;
        }
        __syncthreads();
        if (tid < 84) {
            float* at = sSCR + h*462 + i;
            #pragma unroll
            for (int j = 0; j < 21; j++) at[j*22] = v[j];
        }
    }
    __syncthreads();

    // ---- E: h1 = elu(alpha1 @ gl1 + b1) -> overwrite sGL1 (column-exclusive) ----
    {
        const int c = tid, h = c >> 6;
        unsigned long long acc[10];
        #pragma unroll
        for (int q = 0; q < 10; q++) acc[q] = pk2(0.f, 0.f);
        float acc20 = 0.f;
        const float* aT = sSCR + h*462;
        #pragma unroll 3
        for (int j = 0; j < 21; j++) {
            float g = sGL1[j*256 + c];
            unsigned long long gg = pk2(g, g);
            const unsigned long long* ap = (const unsigned long long*)(aT + j*22);
            #pragma unroll
            for (int q = 0; q < 10; q++) acc[q] = fma2(ap[q], gg, acc[q]);
            acc20 = fmaf(aT[j*22 + 20], g, acc20);
        }
        float bc = sB1[c];
        #pragma unroll
        for (int q = 0; q < 10; q++) {
            float2 v = upk2(acc[q]);
            float v0 = v.x + bc;
            float v1 = v.y + bc;
            v0 = fmaxf(v0, 0.f) + __expf(fminf(v0, 0.f)) - 1.f;   // elu, branchless
            v1 = fmaxf(v1, 0.f) + __expf(fminf(v1, 0.f)) - 1.f;
            sGL1[(2*q  )*256 + c] = v0;
            sGL1[(2*q+1)*256 + c] = v1;
        }
        float v20 = acc20 + bc;
        v20 = fmaxf(v20, 0.f) + __expf(fminf(v20, 0.f)) - 1.f;
        sGL1[20*256 + c] = v20;
    }
    __syncthreads();

    // ---- F: gl2 / gr2 = h1 @ Wl2 / Wr2 (f32x2 packed) ----
    {
        const int d    = tid & 63;
        const int sel  = (tid >> 6) & 1;
        const int half = tid >> 7;
        const float* __restrict__ W = sel ? Wr2 : Wl2;
        float* G = sSCR + (sel ? 1344 : 0);
        const int i0 = half ? 11 : 0;
        unsigned long long acc[11];
        #pragma unroll
        for (int i = 0; i < 11; i++) acc[i] = pk2(0.f, 0.f);
        for (int k = 0; k < 256; k += 4) {
            float w0 = W[(k+0)*64 + d];
            float w1 = W[(k+1)*64 + d];
            float w2 = W[(k+2)*64 + d];
            float w3 = W[(k+3)*64 + d];
            unsigned long long wp01 = pk2(w0, w1);
            unsigned long long wp23 = pk2(w2, w3);
            #pragma unroll
            for (int i = 0; i < 11; i++) {
                if (i0 + i < 21) {
                    ulonglong2 h2 = *(const ulonglong2*)&sGL1[(i0+i)*256 + k];
                    acc[i] = fma2(wp01, h2.x, acc[i]);
                    acc[i] = fma2(wp23, h2.y, acc[i]);
                }
            }
        }
        #pragma unroll
        for (int i = 0; i < 11; i++) {
            if (i0 + i < 21) {
                float2 s = upk2(acc[i]);
                G[(i0+i)*64 + d] = s.x + s.y;
            }
        }
    }
    __syncthreads();

    // ---- A2 precompute: A2[j] = att2 . gl2[j] ----
    {
        const int base = (lane & 7) * 8;
        float4 aA = *(const float4*)&sAtt2[base];
        float4 aB = *(const float4*)&sAtt2[base + 4];
        int j = warp + 8 * (lane >> 3);
        int jc = (j < 21) ? j : 20;
        const float* gl2 = sSCR;
        float4 g0 = *(const float4*)&gl2[jc*64 + base];
        float4 g1 = *(const float4*)&gl2[jc*64 + base + 4];
        float p = aA.x*g0.x + aA.y*g0.y + aA.z*g0.z + aA.w*g0.w
                + aB.x*g1.x + aB.y*g1.y + aB.z*g1.z + aB.w*g1.w;
        p += __shfl_xor_sync(0xffffffffu, p, 4);
        p += __shfl_xor_sync(0xffffffffu, p, 2);
        p += __shfl_xor_sync(0xffffffffu, p, 1);
        if ((lane & 7) == 0 && j < 21) sAj[j] = p;
    }
    __syncthreads();

    // ---- C2: e2[i,j] (1 head, d=64); 4 (i,j)-pairs per warp ----
    {
        const int base = (lane & 7) * 8;
        const int grp  = lane >> 3;
        float4 aA = *(const float4*)&sAtt2[base];
        float4 aB = *(const float4*)&sAtt2[base + 4];
        const float* gl2 = sSCR;
        const float* gr2 = sSCR + 1344;
        float* sE2 = sSCR + 2688;
        for (int i = warp; i < 21; i += 8) {
            float4 r0 = *(const float4*)&gr2[i*64 + base];
            float4 r1 = *(const float4*)&gr2[i*64 + base + 4];
            float Bp = aA.x*r0.x + aA.y*r0.y + aA.z*r0.z + aA.w*r0.w
                     + aB.x*r1.x + aB.y*r1.y + aB.z*r1.z + aB.w*r1.w;
            Bp += __shfl_xor_sync(0xffffffffu, Bp, 4);
            Bp += __shfl_xor_sync(0xffffffffu, Bp, 2);
            Bp += __shfl_xor_sync(0xffffffffu, Bp, 1);
            #pragma unroll
            for (int jb = 0; jb < 21; jb += 4) {
                int j = jb + grp;
                int jc = (j < 21) ? j : 20;
                float4 g0 = *(const float4*)&gl2[jc*64 + base];
                float4 g1 = *(const float4*)&gl2[jc*64 + base + 4];
                float t;
                t  = aA.x * fabsf(g0.x + r0.x);
                t  = fmaf(aA.y, fabsf(g0.y + r0.y), t);
                t  = fmaf(aA.z, fabsf(g0.z + r0.z), t);
                t  = fmaf(aA.w, fabsf(g0.w + r0.w), t);
                t  = fmaf(aB.x, fabsf(g1.x + r1.x), t);
                t  = fmaf(aB.y, fabsf(g1.y + r1.y), t);
                t  = fmaf(aB.z, fabsf(g1.z + r1.z), t);
                t  = fmaf(aB.w, fabsf(g1.w + r1.w), t);
                t += __shfl_xor_sync(0xffffffffu, t, 4);
                t += __shfl_xor_sync(0xffffffffu, t, 2);
                t += __shfl_xor_sync(0xffffffffu, t, 1);
                if ((lane & 7) == 0 && j < 21)
                    sE2[i*21 + j] = fmaf(0.4f, t, 0.6f * (sAj[j] + Bp));
            }
        }
    }
    __syncthreads();

    // ---- softmax2 ----
    if (tid < 21) {
        float* row = sSCR + 2688 + tid*21;
        float m = -1e30f;
        #pragma unroll
        for (int j = 0; j < 21; j++) m = fmaxf(m, row[j]);
        float s = 0.f;
        #pragma unroll
        for (int j = 0; j < 21; j++) { float v = __expf(row[j] - m); row[j] = v; s += v; }
        float inv = 1.f / s;
        #pragma unroll
        for (int j = 0; j < 21; j++) row[j] *= inv;
    }
    __syncthreads();

    // ---- E2: out2 = alpha2 @ gl2 + b2 -> scratch+1344 (over gr2) ----
    {
        const int d  = tid & 63;
        const int iq = tid >> 6;
        const float* gl2 = sSCR;
        const float* al  = sSCR + 2688;
        float* o2 = sSCR + 1344;
        float gcol[21];
        #pragma unroll 3
        for (int j = 0; j < 21; j++) gcol[j] = gl2[j*64 + d];
        float bd = sB2[d];
        for (int i = iq; i < 21; i += 4) {
            const float* ar = al + i*21;
            float acc = 0.f;
            #pragma unroll 7
            for (int j = 0; j < 21; j++) acc = fmaf(ar[j], gcol[j], acc);
            o2[i*64 + d] = acc + bd;
        }
    }
    __syncthreads();

    // ---- mean pool ----
    if (tid < 64) {
        const float* o2 = sSCR + 1344;
        float acc = 0.f;
        #pragma unroll 7
        for (int i = 0; i < 21; i++) acc += o2[i*64 + tid];
        sSCR[tid] = acc * (1.0f / 21.0f);       // nfv @ scratch+0
    }
    __syncthreads();

    // ---- fc1 (64->256) relu ----
    {
        const int c = tid;
        unsigned long long acc = pk2(0.f, 0.f);
        const unsigned long long* nf = (const unsigned long long*)(sSCR);
        #pragma unroll 8
        for (int k = 0; k < 32; k++) {
            unsigned long long wp = pk2(fc1w[(2*k)*256 + c], fc1w[(2*k+1)*256 + c]);
            acc = fma2(wp, nf[k], acc);
        }
        float2 s = upk2(acc);
        sSCR[64 + c] = fmaxf(s.x + s.y + fc1b[c], 0.f);
    }
    __syncthreads();

    // ---- fc2 (256->256) relu ----
    {
        const int c = tid;
        unsigned long long acc = pk2(0.f, 0.f);
        const unsigned long long* f1 = (const unsigned long long*)(sSCR + 64);
        #pragma unroll 8
        for (int k = 0; k < 128; k++) {
            unsigned long long wp = pk2(fc2w[(2*k)*256 + c], fc2w[(2*k+1)*256 + c]);
            acc = fma2(wp, f1[k], acc);
        }
        float2 s = upk2(acc);
        sSCR[320 + c] = fmaxf(s.x + s.y + fc2b[c], 0.f);
    }
    __syncthreads();

    // ---- fc3 (256->2) tanh ----
    if (tid < 64) {
        const int o = tid >> 5;
        const int l = tid & 31;
        const float* f2 = sSCR + 320;
        float acc = 0.f;
        #pragma unroll
        for (int k = l; k < 256; k += 32) acc = fmaf(f2[k], fc3w[k*2 + o], acc);
        #pragma unroll
        for (int off = 16; off; off >>= 1) acc += __shfl_down_sync(0xffffffffu, acc, off);
        if (l == 0) out[b*2 + o] = tanhf(acc + fc3b[o]);
    }
}

extern "C" void kernel_launch(void* const* d_in, const int* in_sizes, int n_in,
                              void* d_out, int out_size) {
    const float* state24 = (const float*)d_in[0];
    const float* Wl1  = (const float*)d_in[1];
    const float* Wr1  = (const float*)d_in[2];
    const float* att1 = (const float*)d_in[3];
    const float* b1   = (const float*)d_in[4];
    const float* Wl2  = (const float*)d_in[5];
    const float* Wr2  = (const float*)d_in[6];
    const float* att2 = (const float*)d_in[7];
    const float* b2   = (const float*)d_in[8];
    const float* fc1w = (const float*)d_in[9];
    const float* fc1b = (const float*)d_in[10];
    const float* fc2w = (const float*)d_in[11];
    const float* fc2b = (const float*)d_in[12];
    const float* fc3w = (const float*)d_in[13];
    const float* fc3b = (const float*)d_in[14];
    float* out = (float*)d_out;

    const int B = in_sizes[0] / 24;
    const size_t smem = SMEM_FLOATS * sizeof(float);   // 45,056 B
    cudaFuncSetAttribute(actor_kernel, cudaFuncAttributeMaxDynamicSharedMemorySize, (int)smem);
    actor_kernel<<<B, NTHREADS, smem>>>(state24, Wl1, Wr1, att1, b1,
                                        Wl2, Wr2, att2, b2,
                                        fc1w, fc1b, fc2w, fc2b, fc3w, fc3b, out);
}

// round 3
// speedup vs baseline: 1.3346x; 1.1431x over previous
#include <cuda_runtime.h>
#include <math.h>

#define NTHREADS 256
#define MAXB 8192

__device__ float g_nfv[MAXB * 64];

// ---- f32x2 packed-FMA helpers (sm_100+) ----
__device__ __forceinline__ unsigned long long pk2(float a, float b) {
    unsigned long long r;
    asm("mov.b64 %0, {%1,%2};" : "=l"(r) : "f"(a), "f"(b));
    return r;
}
__device__ __forceinline__ float2 upk2(unsigned long long v) {
    float2 r;
    asm("mov.b64 {%0,%1}, %2;" : "=f"(r.x), "=f"(r.y) : "l"(v));
    return r;
}
__device__ __forceinline__ unsigned long long fma2(unsigned long long a,
                                                   unsigned long long b,
                                                   unsigned long long c) {
    unsigned long long d;
    asm("fma.rn.f32x2 %0, %1, %2, %3;" : "=l"(d) : "l"(a), "l"(b), "l"(c));
    return d;
}

__device__ __forceinline__ float dot8(float4 a, float4 b, float4 u, float4 v) {
    float p = a.x * u.x;
    p = fmaf(a.y, u.y, p); p = fmaf(a.z, u.z, p); p = fmaf(a.w, u.w, p);
    p = fmaf(b.x, v.x, p); p = fmaf(b.y, v.y, p); p = fmaf(b.z, v.z, p);
    return fmaf(b.w, v.w, p);
}
__device__ __forceinline__ float red8(float p) {
    p += __shfl_xor_sync(0xffffffffu, p, 1);
    p += __shfl_xor_sync(0xffffffffu, p, 2);
    p += __shfl_xor_sync(0xffffffffu, p, 4);
    return p;
}
__device__ __forceinline__ float absdot8(float4 a, float4 b,
                                         float4 g0, float4 g1,
                                         float4 r0, float4 r1) {
    float t;
    t  = a.x * fabsf(g0.x + r0.x);
    t  = fmaf(a.y, fabsf(g0.y + r0.y), t);
    t  = fmaf(a.z, fabsf(g0.z + r0.z), t);
    t  = fmaf(a.w, fabsf(g0.w + r0.w), t);
    t  = fmaf(b.x, fabsf(g1.x + r1.x), t);
    t  = fmaf(b.y, fabsf(g1.y + r1.y), t);
    t  = fmaf(b.z, fabsf(g1.z + r1.z), t);
    t  = fmaf(b.w, fabsf(g1.w + r1.w), t);
    return t;
}

// smem layout (floats)
#define OFF_ATT1 0      // 256
#define OFF_B1   256    // 256
#define OFF_ATT2 512    // 64
#define OFF_B2   576    // 64
#define OFF_WR1  640    // 1792 (dead after C; alphaT [4*504=2016] lives here)
#define OFF_X    2432   // 168
#define OFF_AJ   2600   // 88
#define OFF_GL1  2688   // 5376 (21x256) -> h1 after step E
#define OFF_SCR  8064   // 3200 scratch
#define SMEM_FLOATS 11264
// scratch: e1 [i*84+j*4+h] (1764); layer2: gl2 @0 (1344), gr2 @1344 (1344),
//          e2 @2688 (441), A2 @3136 (21); out2 @1344 after softmax2.

__global__ __launch_bounds__(NTHREADS, 5) void actor_kernel(
    const float* __restrict__ state24,
    const float* __restrict__ Wl1, const float* __restrict__ Wr1,
    const float* __restrict__ att1, const float* __restrict__ b1,
    const float* __restrict__ Wl2, const float* __restrict__ Wr2,
    const float* __restrict__ att2, const float* __restrict__ b2)
{
    extern __shared__ float sm[];
    float* sAtt1 = sm + OFF_ATT1;
    float* sB1   = sm + OFF_B1;
    float* sAtt2 = sm + OFF_ATT2;
    float* sB2   = sm + OFF_B2;
    float* sWr1  = sm + OFF_WR1;
    float* sX    = sm + OFF_X;
    float* sAj   = sm + OFF_AJ;
    float* sGL1  = sm + OFF_GL1;   // later h1
    float* sSCR  = sm + OFF_SCR;
    float* sAlphaT = sm + OFF_WR1; // alias, valid after step C

    const int tid  = threadIdx.x;
    const int lane = tid & 31;
    const int warp = tid >> 5;
    const int b    = blockIdx.x;
    const float* st = state24 + b * 24;

    const int g = lane >> 3, q = lane & 7;
    const int off0 = g * 64 + q * 4;       // head g, dims [q*4, q*4+4)
    const int off1 = off0 + 32;            // head g, dims [32+q*4, ...)
    const int offq0 = q * 4;               // single-head (layer2) mapping
    const int offq1 = q * 4 + 32;

    // ---- consts + Wr1 -> smem, node features ----
    sAtt1[tid] = att1[tid];
    sB1[tid]   = b1[tid];
    if (tid < 64) { sAtt2[tid] = att2[tid]; sB2[tid] = b2[tid]; }
    #pragma unroll
    for (int i = tid; i < 1792; i += NTHREADS) sWr1[i] = Wr1[i];

    if (tid < 21) {
        float f0, f1, f2, f3, f4, f5, f6;
        if (tid < 20) {
            double ang = (-1.6007963267948966 + 0.15707963267948966)
                       + (double)tid * 0.15857963267948968;
            float a = (float)ang;
            f0 = st[tid] * 0.1f;
            f1 = sinf(a); f2 = cosf(a);
            f3 = f4 = f5 = f6 = 0.f;
        } else {
            f0 = f1 = f2 = 0.f;
            f3 = st[20]; f4 = st[21]; f5 = st[22]; f6 = st[23];
        }
        float* xr = sX + tid * 8;
        xr[0]=f0; xr[1]=f1; xr[2]=f2; xr[3]=f3; xr[4]=f4; xr[5]=f5; xr[6]=f6; xr[7]=0.f;
    }
    __syncthreads();

    // ---- B: gl1 = x @ Wl1 (thread = column c) ----
    {
        const int c = tid;
        float wl[7];
        #pragma unroll
        for (int k = 0; k < 7; k++) wl[k] = Wl1[k*256 + c];
        #pragma unroll 3
        for (int i = 0; i < 21; i++) {
            const float* xr = sX + i*8;
            float a = 0.f;
            #pragma unroll
            for (int k = 0; k < 7; k++) a = fmaf(xr[k], wl[k], a);
            sGL1[i*256 + c] = a;
        }
    }
    __syncthreads();

    // ---- Aj: A[j,h] = att1[h] . gl1[j, head h] ----
    {
        float4 aA = *(const float4*)&sAtt1[off0];
        float4 aB = *(const float4*)&sAtt1[off1];
        for (int j = warp; j < 21; j += 8) {
            float4 g0 = *(const float4*)&sGL1[j*256 + off0];
            float4 g1 = *(const float4*)&sGL1[j*256 + off1];
            float p = red8(dot8(aA, aB, g0, g1));
            if (q == 0) sAj[j*4 + g] = p;
        }
    }
    __syncthreads();

    // ---- C: e1[i,j,h] = 0.6(A_j + B_i) + 0.4 * sum_d att|gl_j + gr_i| ----
    {
        float4 aA = *(const float4*)&sAtt1[off0];
        float4 aB = *(const float4*)&sAtt1[off1];
        float* sE1 = sSCR;

        // pass A: i0 = warp, i1 = warp+8 (always valid)
        {
            const int i0 = warp, i1 = warp + 8;
            float4 r00 = {0,0,0,0}, r01 = {0,0,0,0};
            float4 r10 = {0,0,0,0}, r11 = {0,0,0,0};
            #pragma unroll
            for (int m = 0; m < 7; m++) {
                float4 w0 = *(const float4*)&sWr1[m*256 + off0];
                float4 w1 = *(const float4*)&sWr1[m*256 + off1];
                float xa = sX[i0*8 + m], xb = sX[i1*8 + m];
                r00.x = fmaf(xa, w0.x, r00.x); r00.y = fmaf(xa, w0.y, r00.y);
                r00.z = fmaf(xa, w0.z, r00.z); r00.w = fmaf(xa, w0.w, r00.w);
                r01.x = fmaf(xa, w1.x, r01.x); r01.y = fmaf(xa, w1.y, r01.y);
                r01.z = fmaf(xa, w1.z, r01.z); r01.w = fmaf(xa, w1.w, r01.w);
                r10.x = fmaf(xb, w0.x, r10.x); r10.y = fmaf(xb, w0.y, r10.y);
                r10.z = fmaf(xb, w0.z, r10.z); r10.w = fmaf(xb, w0.w, r10.w);
                r11.x = fmaf(xb, w1.x, r11.x); r11.y = fmaf(xb, w1.y, r11.y);
                r11.z = fmaf(xb, w1.z, r11.z); r11.w = fmaf(xb, w1.w, r11.w);
            }
            float Bp0 = red8(dot8(aA, aB, r00, r01));
            float Bp1 = red8(dot8(aA, aB, r10, r11));
            #pragma unroll 3
            for (int j = 0; j < 21; j++) {
                float4 G0 = *(const float4*)&sGL1[j*256 + off0];
                float4 G1 = *(const float4*)&sGL1[j*256 + off1];
                float t0 = absdot8(aA, aB, G0, G1, r00, r01);
                float t1 = absdot8(aA, aB, G0, G1, r10, r11);
                t0 = red8(t0);
                t1 = red8(t1);
                if (q == 0) {
                    float ajv = sAj[j*4 + g];
                    sE1[(i0*21 + j)*4 + g] = fmaf(0.4f, t0, 0.6f * (ajv + Bp0));
                    sE1[(i1*21 + j)*4 + g] = fmaf(0.4f, t1, 0.6f * (ajv + Bp1));
                }
            }
        }
        // pass B: i2 = warp+16 (warps 0..4)
        if (warp < 5) {
            const int i2 = warp + 16;
            float4 r0 = {0,0,0,0}, r1 = {0,0,0,0};
            #pragma unroll
            for (int m = 0; m < 7; m++) {
                float4 w0 = *(const float4*)&sWr1[m*256 + off0];
                float4 w1 = *(const float4*)&sWr1[m*256 + off1];
                float xv = sX[i2*8 + m];
                r0.x = fmaf(xv, w0.x, r0.x); r0.y = fmaf(xv, w0.y, r0.y);
                r0.z = fmaf(xv, w0.z, r0.z); r0.w = fmaf(xv, w0.w, r0.w);
                r1.x = fmaf(xv, w1.x, r1.x); r1.y = fmaf(xv, w1.y, r1.y);
                r1.z = fmaf(xv, w1.z, r1.z); r1.w = fmaf(xv, w1.w, r1.w);
            }
            float Bp = red8(dot8(aA, aB, r0, r1));
            #pragma unroll 3
            for (int j = 0; j < 21; j++) {
                float4 G0 = *(const float4*)&sGL1[j*256 + off0];
                float4 G1 = *(const float4*)&sGL1[j*256 + off1];
                float t = red8(absdot8(aA, aB, G0, G1, r0, r1));
                if (q == 0)
                    sE1[(i2*21 + j)*4 + g] = fmaf(0.4f, t, 0.6f * (sAj[j*4 + g] + Bp));
            }
        }
    }
    __syncthreads();

    // ---- D: softmax over j; write alphaT [h*504 + j*24 + i] over dead Wr1 ----
    if (tid < 84) {
        const int i = tid >> 2, h = tid & 3;
        const float* row = sSCR + i*84 + h;
        float v[21];
        float m = -1e30f;
        #pragma unroll
        for (int j = 0; j < 21; j++) { v[j] = row[j*4]; m = fmaxf(m, v[j]); }
        float s = 0.f;
        #pragma unroll
        for (int j = 0; j < 21; j++) { v[j] = __expf(v[j] - m); s += v[j]; }
        float inv = 1.f / s;
        float* at = sAlphaT + h*504 + i;
        #pragma unroll
        for (int j = 0; j < 21; j++) at[j*24] = v[j] * inv;
    }
    __syncthreads();

    // ---- E: h1 = elu(alpha1 @ gl1 + b1) -> overwrite sGL1 (column-exclusive) ----
    {
        const int c = tid, h = c >> 6;
        unsigned long long acc[10];
        #pragma unroll
        for (int p = 0; p < 10; p++) acc[p] = pk2(0.f, 0.f);
        float acc20 = 0.f;
        const float* aT = sAlphaT + h*504;
        #pragma unroll 3
        for (int j = 0; j < 21; j++) {
            float gv = sGL1[j*256 + c];
            unsigned long long gg = pk2(gv, gv);
            const ulonglong2* ap = (const ulonglong2*)(aT + j*24);
            ulonglong2 p0 = ap[0];
            acc[0] = fma2(p0.x, gg, acc[0]); acc[1] = fma2(p0.y, gg, acc[1]);
            ulonglong2 p1 = ap[1];
            acc[2] = fma2(p1.x, gg, acc[2]); acc[3] = fma2(p1.y, gg, acc[3]);
            ulonglong2 p2 = ap[2];
            acc[4] = fma2(p2.x, gg, acc[4]); acc[5] = fma2(p2.y, gg, acc[5]);
            ulonglong2 p3 = ap[3];
            acc[6] = fma2(p3.x, gg, acc[6]); acc[7] = fma2(p3.y, gg, acc[7]);
            ulonglong2 p4 = ap[4];
            acc[8] = fma2(p4.x, gg, acc[8]); acc[9] = fma2(p4.y, gg, acc[9]);
            acc20 = fmaf(aT[j*24 + 20], gv, acc20);
        }
        float bc = sB1[c];
        #pragma unroll
        for (int p = 0; p < 10; p++) {
            float2 v = upk2(acc[p]);
            float v0 = v.x + bc;
            float v1 = v.y + bc;
            v0 = fmaxf(v0, 0.f) + __expf(fminf(v0, 0.f)) - 1.f;
            v1 = fmaxf(v1, 0.f) + __expf(fminf(v1, 0.f)) - 1.f;
            sGL1[(2*p  )*256 + c] = v0;
            sGL1[(2*p+1)*256 + c] = v1;
        }
        float v20 = acc20 + bc;
        v20 = fmaxf(v20, 0.f) + __expf(fminf(v20, 0.f)) - 1.f;
        sGL1[20*256 + c] = v20;
    }
    __syncthreads();

    // ---- F: gl2 / gr2 = h1 @ Wl2 / Wr2 (f32x2 packed, broadcast LDS) ----
    {
        const int d    = tid & 63;
        const int sel  = (tid >> 6) & 1;
        const int half = tid >> 7;
        const float* __restrict__ W = sel ? Wr2 : Wl2;
        float* G = sSCR + (sel ? 1344 : 0);
        const int i0 = half ? 11 : 0;
        unsigned long long acc[11];
        #pragma unroll
        for (int i = 0; i < 11; i++) acc[i] = pk2(0.f, 0.f);
        for (int k = 0; k < 256; k += 4) {
            float w0 = W[(k+0)*64 + d];
            float w1 = W[(k+1)*64 + d];
            float w2 = W[(k+2)*64 + d];
            float w3 = W[(k+3)*64 + d];
            unsigned long long wp01 = pk2(w0, w1);
            unsigned long long wp23 = pk2(w2, w3);
            #pragma unroll
            for (int i = 0; i < 11; i++) {
                if (i0 + i < 21) {
                    ulonglong2 h2 = *(const ulonglong2*)&sGL1[(i0+i)*256 + k];
                    acc[i] = fma2(wp01, h2.x, acc[i]);
                    acc[i] = fma2(wp23, h2.y, acc[i]);
                }
            }
        }
        #pragma unroll
        for (int i = 0; i < 11; i++) {
            if (i0 + i < 21) {
                float2 s = upk2(acc[i]);
                G[(i0+i)*64 + d] = s.x + s.y;
            }
        }
    }
    __syncthreads();

    // ---- A2: A2[j] = att2 . gl2[j]  (8-lane groups own one j each) ----
    {
        float4 aA = *(const float4*)&sAtt2[offq0];
        float4 aB = *(const float4*)&sAtt2[offq1];
        const float* gl2 = sSCR;
        float* sA2 = sSCR + 3136;
        int j = warp + 8*g;                 // 0..31
        int jc = (j < 21) ? j : 20;
        float4 g0 = *(const float4*)&gl2[jc*64 + offq0];
        float4 g1 = *(const float4*)&gl2[jc*64 + offq1];
        float p = red8(dot8(aA, aB, g0, g1));
        if (q == 0 && j < 21) sA2[j] = p;
    }
    __syncthreads();

    // ---- C2: e2[i,j] single head; 4 j-groups x 8 d-lanes per warp ----
    {
        float4 aA = *(const float4*)&sAtt2[offq0];
        float4 aB = *(const float4*)&sAtt2[offq1];
        const float* gl2 = sSCR;
        const float* gr2 = sSCR + 1344;
        const float* sA2 = sSCR + 3136;
        float* sE2 = sSCR + 2688;
        for (int i = warp; i < 21; i += 8) {
            float4 R0 = *(const float4*)&gr2[i*64 + offq0];
            float4 R1 = *(const float4*)&gr2[i*64 + offq1];
            float Bp = red8(dot8(aA, aB, R0, R1));
            #pragma unroll
            for (int jb = 0; jb < 21; jb += 4) {
                int j = jb + g;
                int jc = (j < 21) ? j : 20;
                float4 G0 = *(const float4*)&gl2[jc*64 + offq0];
                float4 G1 = *(const float4*)&gl2[jc*64 + offq1];
                float t = red8(absdot8(aA, aB, G0, G1, R0, R1));
                if (q == 0 && j < 21)
                    sE2[i*21 + j] = fmaf(0.4f, t, 0.6f * (sA2[j] + Bp));
            }
        }
    }
    __syncthreads();

    // ---- softmax2 ----
    if (tid < 21) {
        float* row = sSCR + 2688 + tid*21;
        float m = -1e30f;
        #pragma unroll
        for (int j = 0; j < 21; j++) m = fmaxf(m, row[j]);
        float s = 0.f;
        #pragma unroll
        for (int j = 0; j < 21; j++) { float v = __expf(row[j] - m); row[j] = v; s += v; }
        float inv = 1.f / s;
        #pragma unroll
        for (int j = 0; j < 21; j++) row[j] *= inv;
    }
    __syncthreads();

    // ---- E2: out2 = alpha2 @ gl2 + b2 -> scratch+1344 (over gr2) ----
    {
        const int d  = tid & 63;
        const int iq = tid >> 6;
        const float* gl2 = sSCR;
        const float* al  = sSCR + 2688;
        float* o2 = sSCR + 1344;
        float gcol[21];
        #pragma unroll 3
        for (int j = 0; j < 21; j++) gcol[j] = gl2[j*64 + d];
        float bd = sB2[d];
        for (int i = iq; i < 21; i += 4) {
            const float* ar = al + i*21;
            float acc = 0.f;
            #pragma unroll 7
            for (int j = 0; j < 21; j++) acc = fmaf(ar[j], gcol[j], acc);
            o2[i*64 + d] = acc + bd;
        }
    }
    __syncthreads();

    // ---- mean pool -> global nfv ----
    if (tid < 64) {
        const float* o2 = sSCR + 1344;
        float acc = 0.f;
        #pragma unroll 7
        for (int i = 0; i < 21; i++) acc += o2[i*64 + tid];
        g_nfv[b*64 + tid] = acc * (1.0f / 21.0f);
    }
}

// ================= FC head kernel: 8 batch rows per block =================
#define FC_ROWS 8

__global__ __launch_bounds__(256) void fc_kernel(
    const float* __restrict__ fc1w, const float* __restrict__ fc1b,
    const float* __restrict__ fc2w, const float* __restrict__ fc2b,
    const float* __restrict__ fc3w, const float* __restrict__ fc3b,
    float* __restrict__ out, int B)
{
    __shared__ float sN [FC_ROWS * 64];
    __shared__ float sF1[FC_ROWS * 256];
    __shared__ float sF2[FC_ROWS * 256];
    const int tid = threadIdx.x;
    const int r0  = blockIdx.x * FC_ROWS;

    if (tid < 128)
        ((float4*)sN)[tid] = *(const float4*)&g_nfv[r0*64 + tid*4];
    __syncthreads();

    // fc1: 64 -> 256
    {
        const int c = tid;
        unsigned long long acc[FC_ROWS];
        #pragma unroll
        for (int r = 0; r < FC_ROWS; r++) acc[r] = pk2(0.f, 0.f);
        #pragma unroll 4
        for (int k = 0; k < 32; k++) {
            unsigned long long wp = pk2(fc1w[(2*k)*256 + c], fc1w[(2*k+1)*256 + c]);
            #pragma unroll
            for (int r = 0; r < FC_ROWS; r++) {
                unsigned long long nv = *(const unsigned long long*)&sN[r*64 + 2*k];
                acc[r] = fma2(wp, nv, acc[r]);
            }
        }
        float bb = fc1b[c];
        #pragma unroll
        for (int r = 0; r < FC_ROWS; r++) {
            float2 s = upk2(acc[r]);
            sF1[r*256 + c] = fmaxf(s.x + s.y + bb, 0.f);
        }
    }
    __syncthreads();

    // fc2: 256 -> 256
    {
        const int c = tid;
        unsigned long long acc[FC_ROWS];
        #pragma unroll
        for (int r = 0; r < FC_ROWS; r++) acc[r] = pk2(0.f, 0.f);
        #pragma unroll 4
        for (int k = 0; k < 128; k++) {
            unsigned long long wp = pk2(fc2w[(2*k)*256 + c], fc2w[(2*k+1)*256 + c]);
            #pragma unroll
            for (int r = 0; r < FC_ROWS; r++) {
                unsigned long long fv = *(const unsigned long long*)&sF1[r*256 + 2*k];
                acc[r] = fma2(wp, fv, acc[r]);
            }
        }
        float bb = fc2b[c];
        #pragma unroll
        for (int r = 0; r < FC_ROWS; r++) {
            float2 s = upk2(acc[r]);
            sF2[r*256 + c] = fmaxf(s.x + s.y + bb, 0.f);
        }
    }
    __syncthreads();

    // fc3: 256 -> 2, tanh.  16 tasks (r,o) on warps 0-3, 8-lane groups.
    const int warp = tid >> 5, lane = tid & 31;
    const int grp = lane >> 3, q = lane & 7;
    const int task = warp * 4 + grp;
    if (task < 16) {
        const int r = task >> 1, o = task & 1;
        float acc = 0.f;
        #pragma unroll
        for (int m = 0; m < 8; m++) {
            int k = m*32 + q*4;
            float4 f = *(const float4*)&sF2[r*256 + k];
            acc = fmaf(f.x, fc3w[(k+0)*2 + o], acc);
            acc = fmaf(f.y, fc3w[(k+1)*2 + o], acc);
            acc = fmaf(f.z, fc3w[(k+2)*2 + o], acc);
            acc = fmaf(f.w, fc3w[(k+3)*2 + o], acc);
        }
        acc += __shfl_xor_sync(0xffffffffu, acc, 1);
        acc += __shfl_xor_sync(0xffffffffu, acc, 2);
        acc += __shfl_xor_sync(0xffffffffu, acc, 4);
        if (q == 0 && r0 + r < B)
            out[(r0 + r)*2 + o] = tanhf(acc + fc3b[o]);
    }
}

extern "C" void kernel_launch(void* const* d_in, const int* in_sizes, int n_in,
                              void* d_out, int out_size) {
    const float* state24 = (const float*)d_in[0];
    const float* Wl1  = (const float*)d_in[1];
    const float* Wr1  = (const float*)d_in[2];
    const float* att1 = (const float*)d_in[3];
    const float* b1   = (const float*)d_in[4];
    const float* Wl2  = (const float*)d_in[5];
    const float* Wr2  = (const float*)d_in[6];
    const float* att2 = (const float*)d_in[7];
    const float* b2   = (const float*)d_in[8];
    const float* fc1w = (const float*)d_in[9];
    const float* fc1b = (const float*)d_in[10];
    const float* fc2w = (const float*)d_in[11];
    const float* fc2b = (const float*)d_in[12];
    const float* fc3w = (const float*)d_in[13];
    const float* fc3b = (const float*)d_in[14];
    float* out = (float*)d_out;

    const int B = in_sizes[0] / 24;
    const size_t smem = SMEM_FLOATS * sizeof(float);   // 45,056 B
    cudaFuncSetAttribute(actor_kernel, cudaFuncAttributeMaxDynamicSharedMemorySize, (int)smem);
    actor_kernel<<<B, NTHREADS, smem>>>(state24, Wl1, Wr1, att1, b1,
                                        Wl2, Wr2, att2, b2);
    fc_kernel<<<(B + FC_ROWS - 1) / FC_ROWS, 256>>>(fc1w, fc1b, fc2w, fc2b,
                                                    fc3w, fc3b, out, B);
}